// round 15
// baseline (speedup 1.0000x reference)
#include <cuda_runtime.h>
#include <cuda_bf16.h>
#include <cuda_fp16.h>
#include <math.h>
#include <cstdint>

#define BB 2
#define SS 2048
#define DD 1024
#define HH 16
#define DKK 64

// ---- fp16 scratch (allocation-free rule: __device__ globals) ----
__device__ __half g_qh[BB * SS * DD], g_ql[BB * SS * DD];        // q split
__device__ __half g_kch[BB * SS * DD], g_kcl[BB * SS * DD];      // gathered k split
__device__ __half g_vch[BB * SS * DD], g_vcl[BB * SS * DD];      // gathered v split
__device__ __half g_wq16[DD * DD], g_wk16[DD * DD];              // weights truncated
__device__ __half g_wv16[DD * DD], g_wo16[DD * DD];
__device__ __half g_qph[BB * SS * DD], g_qpl[BB * SS * DD];      // Q proj hi/lo (pre-scaled)
__device__ __half g_kph[BB * SS * DD];                           // K proj hi
__device__ __half g_vph[BB * SS * DD];                           // V proj hi
__device__ __half g_ah[BB * SS * DD], g_al[BB * SS * DD];        // attention out hi/lo
__device__ int g_cidx[BB * SS];
__device__ int g_cnt[BB];

// ===========================================================================
// helpers
// ===========================================================================
__device__ __forceinline__ uint32_t smem_u32(const void* p) {
    uint32_t a;
    asm("{ .reg .u64 t; cvta.to.shared.u64 t, %1; cvt.u32.u64 %0, t; }"
        : "=r"(a) : "l"(p));
    return a;
}
__device__ __forceinline__ void ldm_x4(uint32_t* r, uint32_t addr) {
    asm volatile("ldmatrix.sync.aligned.m8n8.x4.shared.b16 {%0,%1,%2,%3}, [%4];"
                 : "=r"(r[0]), "=r"(r[1]), "=r"(r[2]), "=r"(r[3]) : "r"(addr));
}
__device__ __forceinline__ void ldm_x4t(uint32_t* r, uint32_t addr) {
    asm volatile("ldmatrix.sync.aligned.m8n8.x4.trans.shared.b16 {%0,%1,%2,%3}, [%4];"
                 : "=r"(r[0]), "=r"(r[1]), "=r"(r[2]), "=r"(r[3]) : "r"(addr));
}
__device__ __forceinline__ void mma16816h(float* d, const uint32_t* a, const uint32_t* b) {
    asm volatile(
        "mma.sync.aligned.m16n8k16.row.col.f32.f16.f16.f32 "
        "{%0,%1,%2,%3}, {%4,%5,%6,%7}, {%8,%9}, {%0,%1,%2,%3};"
        : "+f"(d[0]), "+f"(d[1]), "+f"(d[2]), "+f"(d[3])
        : "r"(a[0]), "r"(a[1]), "r"(a[2]), "r"(a[3]), "r"(b[0]), "r"(b[1]));
}
__device__ __forceinline__ uint32_t pack_h(float x, float y) {
    __half2 t = __floats2half2_rn(x, y);
    return *(uint32_t*)&t;
}
__device__ __forceinline__ void cp16(uint32_t s, const void* g) {
    asm volatile("cp.async.cg.shared.global [%0], [%1], 16;" :: "r"(s), "l"(g));
}
__device__ __forceinline__ void cp_commit() {
    asm volatile("cp.async.commit_group;" ::: "memory");
}
template <int N>
__device__ __forceinline__ void cp_wait() {
    asm volatile("cp.async.wait_group %0;" :: "n"(N) : "memory");
}
// fp16 hi/lo split of 4 floats
__device__ __forceinline__ void split4h(float4 v, uint32_t& h01, uint32_t& h23,
                                        uint32_t& l01, uint32_t& l23) {
    float hx = __half2float(__float2half_rn(v.x));
    float hy = __half2float(__float2half_rn(v.y));
    float hz = __half2float(__float2half_rn(v.z));
    float hw = __half2float(__float2half_rn(v.w));
    h01 = pack_h(v.x, v.y); h23 = pack_h(v.z, v.w);
    l01 = pack_h(v.x - hx, v.y - hy); l23 = pack_h(v.z - hz, v.w - hw);
}

// ===========================================================================
// mask compaction
// ===========================================================================
__global__ __launch_bounds__(256) void compact_kernel(
    const int* __restrict__ mask, int* __restrict__ cidx, int* __restrict__ cnt)
{
    const int b = blockIdx.x;
    const int t = threadIdx.x;
    const int* mb = mask + b * SS;
    int keep[8];
    int c = 0;
#pragma unroll
    for (int e = 0; e < 8; e++) {
        int p = t * 8 + e;
        if (mb[p] == 0) keep[c++] = p;
    }
    __shared__ int sc[256];
    sc[t] = c;
    __syncthreads();
    for (int off = 1; off < 256; off <<= 1) {
        int v = sc[t];
        int add = (t >= off) ? sc[t - off] : 0;
        __syncthreads();
        sc[t] = v + add;
        __syncthreads();
    }
    int ofs = sc[t] - c;
    int* out = cidx + b * SS;
    for (int i = 0; i < c; i++) out[ofs + i] = keep[i];
    if (t == 255) cnt[b] = sc[255];
}

// ===========================================================================
// Fused prep: q split (y=0), weight truncs (y=1..4), K/V gather-split (y=5)
// ===========================================================================
__global__ __launch_bounds__(256) void split_all_kernel(
    const float* __restrict__ q, const float* __restrict__ k,
    const float* __restrict__ v,
    const float* __restrict__ W0, const float* __restrict__ W1,
    const float* __restrict__ W2, const float* __restrict__ W3,
    const int* __restrict__ cidx, const int* __restrict__ cnt,
    __half* __restrict__ qh, __half* __restrict__ ql,
    __half* __restrict__ kh, __half* __restrict__ kl,
    __half* __restrict__ vh, __half* __restrict__ vl,
    __half* __restrict__ w0, __half* __restrict__ w1,
    __half* __restrict__ w2, __half* __restrict__ w3)
{
    const int sel = blockIdx.y;
    if (sel == 0) {
        int i = (blockIdx.x * 256 + threadIdx.x) * 4;
        uint32_t a, b2, c, d;
        split4h(*(const float4*)(q + i), a, b2, c, d);
        *(uint32_t*)(qh + i)     = a;
        *(uint32_t*)(qh + i + 2) = b2;
        *(uint32_t*)(ql + i)     = c;
        *(uint32_t*)(ql + i + 2) = d;
    } else if (sel <= 4) {
        if (blockIdx.x >= 1024) return;
        const int w = sel - 1;
        const float* in = (w == 0) ? W0 : (w == 1) ? W1 : (w == 2) ? W2 : W3;
        __half* hi = (w == 0) ? w0 : (w == 1) ? w1 : (w == 2) ? w2 : w3;
        int i = (blockIdx.x * 256 + threadIdx.x) * 4;
        float4 vv = *(const float4*)(in + i);
        *(uint32_t*)(hi + i)     = pack_h(vv.x, vv.y);
        *(uint32_t*)(hi + i + 2) = pack_h(vv.z, vv.w);
    } else {
        const int b = blockIdx.x >> 11;
        const int i = blockIdx.x & (SS - 1);
        if (i >= __ldg(cnt + b)) return;
        const int src = __ldg(cidx + b * SS + i);
        const size_t goff = ((size_t)b * SS + src) * DD + threadIdx.x * 4;
        const size_t doff = ((size_t)b * SS + i) * DD + threadIdx.x * 4;
        uint32_t a0, a1, a2, a3;
        split4h(*(const float4*)(k + goff), a0, a1, a2, a3);
        *(uint32_t*)(kh + doff)     = a0;
        *(uint32_t*)(kh + doff + 2) = a1;
        *(uint32_t*)(kl + doff)     = a2;
        *(uint32_t*)(kl + doff + 2) = a3;
        split4h(*(const float4*)(v + goff), a0, a1, a2, a3);
        *(uint32_t*)(vh + doff)     = a0;
        *(uint32_t*)(vh + doff + 2) = a1;
        *(uint32_t*)(vl + doff)     = a2;
        *(uint32_t*)(vl + doff + 2) = a3;
    }
}

// ===========================================================================
// fp16x2 GEMM with cp.async double-buffer: C = (Ah+Al) @ Wh + bias
// OUTF: 1 = f32, 2 = fp16 hi/lo scaled by 0.125, 3 = fp16 hi
// ===========================================================================
#define AP 40
#define BP 136

#define G_AH 0
#define G_AL 10240
#define G_BH 20480
#define G_STAGE 29184
#define G_SMEM (2 * G_STAGE)   // 58368

template <int OUTF>
__device__ __forceinline__ void gemm_body16h(
    const __half* __restrict__ Ah_, const __half* __restrict__ Al_,
    const __half* __restrict__ Bh_,
    const float* __restrict__ bias,
    float* __restrict__ Cf,
    __half* __restrict__ Chh, __half* __restrict__ Chl,
    int M, int N, int K, int bx, int by)
{
    extern __shared__ char dsm[];
    const uint32_t sb = smem_u32(dsm);

    const int tid = threadIdx.x;
    const int wid = tid >> 5;
    const int lid = tid & 31;
    const int m0 = by * 128;
    const int n0 = bx * 128;
    const int wm = (wid & 3) * 32;
    const int wn = (wid >> 2) * 64;

    const int lrow = (lid & 7) + ((lid >> 3) & 1) * 8;
    const int lsel = (lid >> 4) * 8;

    const int arow = tid >> 1;
    const int acol = (tid & 1) * 16;
    const int bk = tid >> 3;
    const int bnb = (tid & 7) * 16;

    const __half* pAh = Ah_ + (size_t)(m0 + arow) * K + acol;
    const __half* pAl = Al_ + (size_t)(m0 + arow) * K + acol;
    const __half* pBh = Bh_ + n0 + bnb;

    const uint32_t sA_off = (uint32_t)(arow * AP + acol) * 2;
    const uint32_t sB_off = (uint32_t)(bk * BP + bnb) * 2;

    float acc[2][8][4];
#pragma unroll
    for (int i = 0; i < 2; i++)
#pragma unroll
        for (int j = 0; j < 8; j++)
#pragma unroll
            for (int r = 0; r < 4; r++) acc[i][j][r] = 0.f;

    const int nchunks = K / 32;

    {
        const uint32_t st = sb;
        cp16(st + G_AH + sA_off,      pAh);
        cp16(st + G_AH + sA_off + 16, pAh + 8);
        cp16(st + G_AL + sA_off,      pAl);
        cp16(st + G_AL + sA_off + 16, pAl + 8);
        const size_t roff = (size_t)bk * N;
        cp16(st + G_BH + sB_off,      pBh + roff);
        cp16(st + G_BH + sB_off + 16, pBh + roff + 8);
        cp_commit();
    }

    for (int c = 0; c < nchunks; c++) {
        if (c + 1 < nchunks) {
            const uint32_t st = sb + ((c + 1) & 1) * G_STAGE;
            const int kb = (c + 1) * 32;
            cp16(st + G_AH + sA_off,      pAh + kb);
            cp16(st + G_AH + sA_off + 16, pAh + kb + 8);
            cp16(st + G_AL + sA_off,      pAl + kb);
            cp16(st + G_AL + sA_off + 16, pAl + kb + 8);
            const size_t roff = (size_t)(kb + bk) * N;
            cp16(st + G_BH + sB_off,      pBh + roff);
            cp16(st + G_BH + sB_off + 16, pBh + roff + 8);
            cp_commit();
            cp_wait<1>();
        } else {
            cp_wait<0>();
        }
        __syncthreads();

        const uint32_t st = sb + (c & 1) * G_STAGE;
        const uint32_t aBaseH = st + G_AH, aBaseL = st + G_AL;
        const uint32_t bBaseH = st + G_BH;

#pragma unroll
        for (int ks = 0; ks < 2; ks++) {
            const int kk = ks * 16;
            uint32_t aH[2][4], aL[2][4];
#pragma unroll
            for (int mt = 0; mt < 2; mt++) {
                uint32_t off = (uint32_t)((wm + mt * 16 + lrow) * AP + kk + lsel) * 2;
                ldm_x4(aH[mt], aBaseH + off);
                ldm_x4(aL[mt], aBaseL + off);
            }
#pragma unroll
            for (int jp = 0; jp < 4; jp++) {
                uint32_t bH[4];
                uint32_t boff = (uint32_t)((kk + lrow) * BP + wn + jp * 16 + lsel) * 2;
                ldm_x4t(bH, bBaseH + boff);
#pragma unroll
                for (int nt = 0; nt < 2; nt++) {
#pragma unroll
                    for (int mt = 0; mt < 2; mt++) {
                        float* d = acc[mt][jp * 2 + nt];
                        mma16816h(d, aH[mt], bH + nt * 2);
                        mma16816h(d, aL[mt], bH + nt * 2);
                    }
                }
            }
        }
        __syncthreads();
    }

#pragma unroll
    for (int mt = 0; mt < 2; mt++) {
        const int row = m0 + wm + mt * 16 + (lid >> 2);
#pragma unroll
        for (int nt8 = 0; nt8 < 8; nt8++) {
            const int col = n0 + wn + nt8 * 8 + (lid & 3) * 2;
            float b0 = __ldg(bias + col);
            float b1 = __ldg(bias + col + 1);
            float v00 = acc[mt][nt8][0] + b0, v01 = acc[mt][nt8][1] + b1;
            float v10 = acc[mt][nt8][2] + b0, v11 = acc[mt][nt8][3] + b1;
            if (OUTF == 1) {
                *(float2*)(Cf + (size_t)row * N + col)       = make_float2(v00, v01);
                *(float2*)(Cf + (size_t)(row + 8) * N + col) = make_float2(v10, v11);
            } else if (OUTF == 2) {
                v00 *= 0.125f; v01 *= 0.125f; v10 *= 0.125f; v11 *= 0.125f;
                float h00 = __half2float(__float2half_rn(v00));
                float h01 = __half2float(__float2half_rn(v01));
                float h10 = __half2float(__float2half_rn(v10));
                float h11 = __half2float(__float2half_rn(v11));
                *(uint32_t*)(Chh + (size_t)row * N + col)       = pack_h(v00, v01);
                *(uint32_t*)(Chl + (size_t)row * N + col)       = pack_h(v00 - h00, v01 - h01);
                *(uint32_t*)(Chh + (size_t)(row + 8) * N + col) = pack_h(v10, v11);
                *(uint32_t*)(Chl + (size_t)(row + 8) * N + col) = pack_h(v10 - h10, v11 - h11);
            } else {
                *(uint32_t*)(Chh + (size_t)row * N + col)       = pack_h(v00, v01);
                *(uint32_t*)(Chh + (size_t)(row + 8) * N + col) = pack_h(v10, v11);
            }
        }
    }
}

__global__ __launch_bounds__(256, 2) void gemm16_q_kernel(
    const __half* Ah_, const __half* Al_, const __half* Bh_,
    const float* bias, __half* Chh, __half* Chl, int M, int N, int K)
{
    gemm_body16h<2>(Ah_, Al_, Bh_, bias, nullptr, Chh, Chl, M, N, K,
                    blockIdx.x, blockIdx.y);
}

__global__ __launch_bounds__(256, 2) void gemm16_kv_kernel(
    const __half* KAh, const __half* KAl,
    const __half* VAh, const __half* VAl,
    const __half* WKh, const __half* WVh,
    const float* bk, const float* bv,
    __half* KCh, __half* VCh,
    const int* cnt, int M, int N, int K)
{
    const int m0 = blockIdx.y * 128;
    const int b = m0 >> 11;
    if ((m0 & (SS - 1)) >= __ldg(cnt + b)) return;
    if (blockIdx.z == 0)
        gemm_body16h<3>(KAh, KAl, WKh, bk, nullptr, KCh, nullptr, M, N, K,
                        blockIdx.x, blockIdx.y);
    else
        gemm_body16h<3>(VAh, VAl, WVh, bv, nullptr, VCh, nullptr, M, N, K,
                        blockIdx.x, blockIdx.y);
}

__global__ __launch_bounds__(256, 2) void gemm16_f32out_kernel(
    const __half* Ah_, const __half* Al_, const __half* Bh_,
    const float* bias, float* Cf, int M, int N, int K)
{
    gemm_body16h<1>(Ah_, Al_, Bh_, bias, Cf, nullptr, nullptr, M, N, K,
                    blockIdx.x, blockIdx.y);
}

// ===========================================================================
// fp16x2 flash attention over compacted K/V (unchanged math from R14;
// epilogue now emits fp16 hi/lo).
// ===========================================================================
#define QP 72
#define KVP 72

#define AT_QH 0
#define AT_QL (AT_QH + 128 * QP * 2)
#define AT_ST0 (AT_QL + 128 * QP * 2)
#define ATK 0
#define ATV (64 * KVP * 2)
#define AT_KV_STAGE (2 * 64 * KVP * 2)
#define AT_SMEM (AT_ST0 + 2 * AT_KV_STAGE)  // 73728

__global__ __launch_bounds__(256, 2) void attn_mma_kernel(
    const __half* __restrict__ Qh_, const __half* __restrict__ Ql_,
    const __half* __restrict__ Kh_, const __half* __restrict__ Vh_,
    const int* __restrict__ cnt,
    __half* __restrict__ Oh_, __half* __restrict__ Ol_)
{
    extern __shared__ char smem[];
    const uint32_t sb = smem_u32(smem);
    uint16_t* sQh = (uint16_t*)(smem + AT_QH);
    uint16_t* sQl = (uint16_t*)(smem + AT_QL);
    const uint32_t qhB = sb + AT_QH;
    const uint32_t qlB = sb + AT_QL;

    const int tid = threadIdx.x;
    const int wid = tid >> 5;
    const int lid = tid & 31;
    const int b = blockIdx.y >> 4;
    const int h = blockIdx.y & 15;
    const int q0 = blockIdx.x << 7;

    const int lrow = (lid & 7) + ((lid >> 3) & 1) * 8;
    const int lsel = (lid >> 4) * 8;
    const int qr = lid >> 2;
    const int qc = (lid & 3) * 2;

    const size_t headoff = (size_t)h * DKK;

    const int cntb = __ldg(cnt + b);
    const int ntiles = (cntb + 63) >> 6;

    const int kvr0 = tid >> 3;
    const int kvc0 = (tid & 7) * 8;
    const size_t kvg0 = (size_t)kvr0 * DD + kvc0;
    const size_t kvg1 = (size_t)(kvr0 + 32) * DD + kvc0;
    const uint32_t kvs0 = (uint32_t)(kvr0 * KVP + kvc0) * 2;
    const uint32_t kvs1 = (uint32_t)((kvr0 + 32) * KVP + kvc0) * 2;

    const __half* Kh0 = Kh_ + (size_t)b * SS * DD + headoff;
    const __half* Vh0 = Vh_ + (size_t)b * SS * DD + headoff;

    // ---- load Q tile (fp16 hi/lo, pre-scaled) ----
    {
        const __half* Qbh = Qh_ + ((size_t)b * SS + q0) * DD + headoff;
        const __half* Qbl = Ql_ + ((size_t)b * SS + q0) * DD + headoff;
#pragma unroll
        for (int p = 0; p < 4; p++) {
            int u = tid + p * 256;
            int r = u >> 3;
            int c8 = (u & 7) * 8;
            *(uint4*)(sQh + r * QP + c8) = *(const uint4*)(Qbh + (size_t)r * DD + c8);
            *(uint4*)(sQl + r * QP + c8) = *(const uint4*)(Qbl + (size_t)r * DD + c8);
        }
    }

    // ---- prefetch tile 0 ----
    {
        const uint32_t st = sb + AT_ST0;
        cp16(st + ATK + kvs0, Kh0 + kvg0);
        cp16(st + ATK + kvs1, Kh0 + kvg1);
        cp16(st + ATV + kvs0, Vh0 + kvg0);
        cp16(st + ATV + kvs1, Vh0 + kvg1);
        cp_commit();
    }

    float o[8][4];
#pragma unroll
    for (int j = 0; j < 8; j++)
#pragma unroll
        for (int r = 0; r < 4; r++) o[j][r] = 0.f;
    float m0v = -3.0e38f, m1v = -3.0e38f, l0v = 0.f, l1v = 0.f;

    for (int kt = 0; kt < ntiles; kt++) {
        const int kv0 = kt * 64;
        if (kt + 1 < ntiles) {
            const uint32_t st = sb + AT_ST0 + ((kt + 1) & 1) * AT_KV_STAGE;
            const size_t gb = (size_t)(kv0 + 64) * DD;
            cp16(st + ATK + kvs0, Kh0 + gb + kvg0);
            cp16(st + ATK + kvs1, Kh0 + gb + kvg1);
            cp16(st + ATV + kvs0, Vh0 + gb + kvg0);
            cp16(st + ATV + kvs1, Vh0 + gb + kvg1);
            cp_commit();
            cp_wait<1>();
        } else {
            cp_wait<0>();
        }
        __syncthreads();

        const uint32_t st = sb + AT_ST0 + (kt & 1) * AT_KV_STAGE;
        const uint32_t khB = st + ATK;
        const uint32_t vhB = st + ATV;

        // ---- S = (Qh + Ql) @ Kh^T ----
        float s[8][4];
#pragma unroll
        for (int j = 0; j < 8; j++)
#pragma unroll
            for (int r = 0; r < 4; r++) s[j][r] = 0.f;

#pragma unroll
        for (int k = 0; k < 4; k++) {
            uint32_t qh[4], ql[4];
            uint32_t qoff = (uint32_t)((wid * 16 + lrow) * QP + k * 16 + lsel) * 2;
            ldm_x4(qh, qhB + qoff);
            ldm_x4(ql, qlB + qoff);
#pragma unroll
            for (int nb = 0; nb < 4; nb++) {
                uint32_t kh[4];
                uint32_t koff = (uint32_t)((nb * 16 + lrow) * KVP + k * 16 + lsel) * 2;
                ldm_x4(kh, khB + koff);
                uint32_t b0[2] = {kh[0], kh[2]}, b1[2] = {kh[1], kh[3]};
                mma16816h(s[nb * 2], qh, b0);
                mma16816h(s[nb * 2], ql, b0);
                mma16816h(s[nb * 2 + 1], qh, b1);
                mma16816h(s[nb * 2 + 1], ql, b1);
            }
        }

        // ---- padding mask ----
#pragma unroll
        for (int j = 0; j < 8; j++) {
            int col0 = kv0 + j * 8 + qc;
            float mk0 = (col0 < cntb) ? 0.f : -1.0e10f;
            float mk1 = (col0 + 1 < cntb) ? 0.f : -1.0e10f;
            s[j][0] += mk0; s[j][1] += mk1;
            s[j][2] += mk0; s[j][3] += mk1;
        }

        // ---- warp-local online softmax ----
        float mt0 = -3.0e38f, mt1 = -3.0e38f;
#pragma unroll
        for (int j = 0; j < 8; j++) {
            mt0 = fmaxf(mt0, fmaxf(s[j][0], s[j][1]));
            mt1 = fmaxf(mt1, fmaxf(s[j][2], s[j][3]));
        }
        mt0 = fmaxf(mt0, __shfl_xor_sync(0xFFFFFFFF, mt0, 1));
        mt0 = fmaxf(mt0, __shfl_xor_sync(0xFFFFFFFF, mt0, 2));
        mt1 = fmaxf(mt1, __shfl_xor_sync(0xFFFFFFFF, mt1, 1));
        mt1 = fmaxf(mt1, __shfl_xor_sync(0xFFFFFFFF, mt1, 2));

        float mn0 = fmaxf(m0v, mt0), mn1 = fmaxf(m1v, mt1);
        float corr0 = __expf(m0v - mn0), corr1 = __expf(m1v - mn1);
        m0v = mn0; m1v = mn1;

        float ts0 = 0.f, ts1 = 0.f;
#pragma unroll
        for (int j = 0; j < 8; j++) {
            s[j][0] = __expf(s[j][0] - mn0);
            s[j][1] = __expf(s[j][1] - mn0);
            s[j][2] = __expf(s[j][2] - mn1);
            s[j][3] = __expf(s[j][3] - mn1);
            ts0 += s[j][0] + s[j][1];
            ts1 += s[j][2] + s[j][3];
        }
        ts0 += __shfl_xor_sync(0xFFFFFFFF, ts0, 1);
        ts0 += __shfl_xor_sync(0xFFFFFFFF, ts0, 2);
        ts1 += __shfl_xor_sync(0xFFFFFFFF, ts1, 1);
        ts1 += __shfl_xor_sync(0xFFFFFFFF, ts1, 2);
        l0v = l0v * corr0 + ts0;
        l1v = l1v * corr1 + ts1;

#pragma unroll
        for (int j = 0; j < 8; j++) {
            o[j][0] *= corr0; o[j][1] *= corr0;
            o[j][2] *= corr1; o[j][3] *= corr1;
        }

        // ---- O += (Ph + Pl) @ Vh ----
#pragma unroll
        for (int t = 0; t < 4; t++) {
            uint32_t pah[4], pal[4];
            {
                float p00 = s[2 * t][0],     p01 = s[2 * t][1];
                float p10 = s[2 * t][2],     p11 = s[2 * t][3];
                float p20 = s[2 * t + 1][0], p21 = s[2 * t + 1][1];
                float p30 = s[2 * t + 1][2], p31 = s[2 * t + 1][3];
                pah[0] = pack_h(p00, p01);
                pah[1] = pack_h(p10, p11);
                pah[2] = pack_h(p20, p21);
                pah[3] = pack_h(p30, p31);
                __half2* hb;
                hb = (__half2*)&pah[0];
                pal[0] = pack_h(p00 - __half2float(hb->x), p01 - __half2float(hb->y));
                hb = (__half2*)&pah[1];
                pal[1] = pack_h(p10 - __half2float(hb->x), p11 - __half2float(hb->y));
                hb = (__half2*)&pah[2];
                pal[2] = pack_h(p20 - __half2float(hb->x), p21 - __half2float(hb->y));
                hb = (__half2*)&pah[3];
                pal[3] = pack_h(p30 - __half2float(hb->x), p31 - __half2float(hb->y));
            }
#pragma unroll
            for (int nb = 0; nb < 4; nb++) {
                uint32_t vh[4];
                uint32_t voff = (uint32_t)((t * 16 + lrow) * KVP + nb * 16 + lsel) * 2;
                ldm_x4t(vh, vhB + voff);
                mma16816h(o[nb * 2], pah, vh);
                mma16816h(o[nb * 2], pal, vh);
                mma16816h(o[nb * 2 + 1], pah, vh + 2);
                mma16816h(o[nb * 2 + 1], pal, vh + 2);
            }
        }
        __syncthreads();
    }

    // ---- epilogue: normalize, fp16 hi/lo for out-proj ----
    float inv0 = 1.f / l0v, inv1 = 1.f / l1v;
    const int r0g = q0 + wid * 16 + qr;
#pragma unroll
    for (int j = 0; j < 8; j++) {
        const size_t col = headoff + j * 8 + qc;
        float v00 = o[j][0] * inv0, v01 = o[j][1] * inv0;
        float v10 = o[j][2] * inv1, v11 = o[j][3] * inv1;
        float h00 = __half2float(__float2half_rn(v00));
        float h01 = __half2float(__float2half_rn(v01));
        float h10 = __half2float(__float2half_rn(v10));
        float h11 = __half2float(__float2half_rn(v11));
        *(uint32_t*)(Oh_ + ((size_t)b * SS + r0g) * DD + col)     = pack_h(v00, v01);
        *(uint32_t*)(Ol_ + ((size_t)b * SS + r0g) * DD + col)     = pack_h(v00 - h00, v01 - h01);
        *(uint32_t*)(Oh_ + ((size_t)b * SS + r0g + 8) * DD + col) = pack_h(v10, v11);
        *(uint32_t*)(Ol_ + ((size_t)b * SS + r0g + 8) * DD + col) = pack_h(v10 - h10, v11 - h11);
    }
}

// ---------------------------------------------------------------------------
extern "C" void kernel_launch(void* const* d_in, const int* in_sizes, int n_in,
                              void* d_out, int out_size)
{
    const float* q    = (const float*)d_in[0];
    const float* k    = (const float*)d_in[1];
    const float* v    = (const float*)d_in[2];
    const int*   mask = (const int*)d_in[3];
    const float* Wq   = (const float*)d_in[4];
    const float* bq   = (const float*)d_in[5];
    const float* Wk   = (const float*)d_in[6];
    const float* bk   = (const float*)d_in[7];
    const float* Wv   = (const float*)d_in[8];
    const float* bv   = (const float*)d_in[9];
    const float* Wo   = (const float*)d_in[10];
    const float* bo   = (const float*)d_in[11];
    float* out = (float*)d_out;

    __half *qh, *ql, *kch, *kcl, *vch, *vcl;
    __half *wq16, *wk16, *wv16, *wo16;
    __half *qph, *qpl, *kph, *vph, *ah, *al;
    int *cidx, *cnt;
    cudaGetSymbolAddress((void**)&qh, g_qh);     cudaGetSymbolAddress((void**)&ql, g_ql);
    cudaGetSymbolAddress((void**)&kch, g_kch);   cudaGetSymbolAddress((void**)&kcl, g_kcl);
    cudaGetSymbolAddress((void**)&vch, g_vch);   cudaGetSymbolAddress((void**)&vcl, g_vcl);
    cudaGetSymbolAddress((void**)&wq16, g_wq16); cudaGetSymbolAddress((void**)&wk16, g_wk16);
    cudaGetSymbolAddress((void**)&wv16, g_wv16); cudaGetSymbolAddress((void**)&wo16, g_wo16);
    cudaGetSymbolAddress((void**)&qph, g_qph);   cudaGetSymbolAddress((void**)&qpl, g_qpl);
    cudaGetSymbolAddress((void**)&kph, g_kph);
    cudaGetSymbolAddress((void**)&vph, g_vph);
    cudaGetSymbolAddress((void**)&ah, g_ah);     cudaGetSymbolAddress((void**)&al, g_al);
    cudaGetSymbolAddress((void**)&cidx, g_cidx);
    cudaGetSymbolAddress((void**)&cnt, g_cnt);

    cudaFuncSetAttribute(gemm16_q_kernel,
                         cudaFuncAttributeMaxDynamicSharedMemorySize, G_SMEM);
    cudaFuncSetAttribute(gemm16_kv_kernel,
                         cudaFuncAttributeMaxDynamicSharedMemorySize, G_SMEM);
    cudaFuncSetAttribute(gemm16_f32out_kernel,
                         cudaFuncAttributeMaxDynamicSharedMemorySize, G_SMEM);
    cudaFuncSetAttribute(attn_mma_kernel,
                         cudaFuncAttributeMaxDynamicSharedMemorySize, AT_SMEM);

    compact_kernel<<<BB, 256>>>(mask, cidx, cnt);
    split_all_kernel<<<dim3(4096, 6), 256>>>(q, k, v, Wq, Wk, Wv, Wo, cidx, cnt,
                                             qh, ql, kch, kcl, vch, vcl,
                                             wq16, wk16, wv16, wo16);

    dim3 gb(DD / 128, (BB * SS) / 128);   // (8, 32)
    gemm16_q_kernel<<<gb, 256, G_SMEM>>>(qh, ql, wq16, bq, qph, qpl, BB * SS, DD, DD);
    gemm16_kv_kernel<<<dim3(8, 32, 2), 256, G_SMEM>>>(kch, kcl, vch, vcl,
                                                      wk16, wv16, bk, bv,
                                                      kph, vph, cnt, BB * SS, DD, DD);

    attn_mma_kernel<<<dim3(SS / 128, BB * HH), 256, AT_SMEM>>>(
        qph, qpl, kph, vph, cnt, ah, al);

    gemm16_f32out_kernel<<<gb, 256, G_SMEM>>>(ah, al, wo16, bo, out, BB * SS, DD, DD);
}

// round 16
// speedup vs baseline: 1.2883x; 1.2883x over previous
#include <cuda_runtime.h>
#include <cuda_bf16.h>
#include <cuda_fp16.h>
#include <math.h>
#include <cstdint>

#define BB 2
#define SS 2048
#define DD 1024
#define HH 16
#define DKK 64

// ---- scratch (allocation-free rule: __device__ globals) ----
__device__ __nv_bfloat16 g_qh[BB * SS * DD], g_ql[BB * SS * DD];
__device__ __nv_bfloat16 g_kc_h[BB * SS * DD], g_kc_l[BB * SS * DD];
__device__ __nv_bfloat16 g_vc_h[BB * SS * DD], g_vc_l[BB * SS * DD];
__device__ __nv_bfloat16 g_wqh[DD * DD], g_wql[DD * DD];
__device__ __nv_bfloat16 g_wkh[DD * DD], g_wkl[DD * DD];
__device__ __nv_bfloat16 g_wvh[DD * DD], g_wvl[DD * DD];
__device__ __nv_bfloat16 g_woh[DD * DD], g_wol[DD * DD];
__device__ __half g_qph[BB * SS * DD], g_qpl[BB * SS * DD];   // Q proj fp16 hi/lo (pre-scaled)
__device__ __half g_kph[BB * SS * DD];                         // K proj fp16 hi only
__device__ __half g_vph[BB * SS * DD];                         // V proj fp16 hi only
__device__ __nv_bfloat16 g_ah[BB * SS * DD], g_al[BB * SS * DD];
__device__ int g_cidx[BB * SS];
__device__ int g_cnt[BB];

// ===========================================================================
// helpers
// ===========================================================================
__device__ __forceinline__ uint32_t smem_u32(const void* p) {
    uint32_t a;
    asm("{ .reg .u64 t; cvta.to.shared.u64 t, %1; cvt.u32.u64 %0, t; }"
        : "=r"(a) : "l"(p));
    return a;
}
__device__ __forceinline__ void ldm_x4(uint32_t* r, uint32_t addr) {
    asm volatile("ldmatrix.sync.aligned.m8n8.x4.shared.b16 {%0,%1,%2,%3}, [%4];"
                 : "=r"(r[0]), "=r"(r[1]), "=r"(r[2]), "=r"(r[3]) : "r"(addr));
}
__device__ __forceinline__ void ldm_x4t(uint32_t* r, uint32_t addr) {
    asm volatile("ldmatrix.sync.aligned.m8n8.x4.trans.shared.b16 {%0,%1,%2,%3}, [%4];"
                 : "=r"(r[0]), "=r"(r[1]), "=r"(r[2]), "=r"(r[3]) : "r"(addr));
}
// bf16 MMA
__device__ __forceinline__ void mma16816(float* d, const uint32_t* a, const uint32_t* b) {
    asm volatile(
        "mma.sync.aligned.m16n8k16.row.col.f32.bf16.bf16.f32 "
        "{%0,%1,%2,%3}, {%4,%5,%6,%7}, {%8,%9}, {%0,%1,%2,%3};"
        : "+f"(d[0]), "+f"(d[1]), "+f"(d[2]), "+f"(d[3])
        : "r"(a[0]), "r"(a[1]), "r"(a[2]), "r"(a[3]), "r"(b[0]), "r"(b[1]));
}
// fp16 MMA
__device__ __forceinline__ void mma16816h(float* d, const uint32_t* a, const uint32_t* b) {
    asm volatile(
        "mma.sync.aligned.m16n8k16.row.col.f32.f16.f16.f32 "
        "{%0,%1,%2,%3}, {%4,%5,%6,%7}, {%8,%9}, {%0,%1,%2,%3};"
        : "+f"(d[0]), "+f"(d[1]), "+f"(d[2]), "+f"(d[3])
        : "r"(a[0]), "r"(a[1]), "r"(a[2]), "r"(a[3]), "r"(b[0]), "r"(b[1]));
}
__device__ __forceinline__ uint32_t pack_h(float x, float y) {
    __half2 t = __floats2half2_rn(x, y);
    return *(uint32_t*)&t;
}
__device__ __forceinline__ void cp16(uint32_t s, const void* g) {
    asm volatile("cp.async.cg.shared.global [%0], [%1], 16;" :: "r"(s), "l"(g));
}
__device__ __forceinline__ void cp_commit() {
    asm volatile("cp.async.commit_group;" ::: "memory");
}
template <int N>
__device__ __forceinline__ void cp_wait() {
    asm volatile("cp.async.wait_group %0;" :: "n"(N) : "memory");
}
__device__ __forceinline__ void split4(float4 v, uint32_t& h01, uint32_t& h23,
                                       uint32_t& l01, uint32_t& l23) {
    __nv_bfloat162 h0 = __floats2bfloat162_rn(v.x, v.y);
    __nv_bfloat162 h1 = __floats2bfloat162_rn(v.z, v.w);
    __nv_bfloat162 l0 = __floats2bfloat162_rn(v.x - __bfloat162float(h0.x),
                                              v.y - __bfloat162float(h0.y));
    __nv_bfloat162 l1 = __floats2bfloat162_rn(v.z - __bfloat162float(h1.x),
                                              v.w - __bfloat162float(h1.y));
    h01 = *(uint32_t*)&h0; h23 = *(uint32_t*)&h1;
    l01 = *(uint32_t*)&l0; l23 = *(uint32_t*)&l1;
}

// ===========================================================================
// mask compaction
// ===========================================================================
__global__ __launch_bounds__(256) void compact_kernel(
    const int* __restrict__ mask, int* __restrict__ cidx, int* __restrict__ cnt)
{
    const int b = blockIdx.x;
    const int t = threadIdx.x;
    const int* mb = mask + b * SS;
    int keep[8];
    int c = 0;
#pragma unroll
    for (int e = 0; e < 8; e++) {
        int p = t * 8 + e;
        if (mb[p] == 0) keep[c++] = p;
    }
    __shared__ int sc[256];
    sc[t] = c;
    __syncthreads();
    for (int off = 1; off < 256; off <<= 1) {
        int v = sc[t];
        int add = (t >= off) ? sc[t - off] : 0;
        __syncthreads();
        sc[t] = v + add;
        __syncthreads();
    }
    int ofs = sc[t] - c;
    int* out = cidx + b * SS;
    for (int i = 0; i < c; i++) out[ofs + i] = keep[i];
    if (t == 255) cnt[b] = sc[255];
}

// ===========================================================================
// Fused prep: q split (y=0), weight splits (y=1..4), K/V gather-split (y=5)
// ===========================================================================
__global__ __launch_bounds__(256) void split_all_kernel(
    const float* __restrict__ q, const float* __restrict__ k,
    const float* __restrict__ v,
    const float* __restrict__ W0, const float* __restrict__ W1,
    const float* __restrict__ W2, const float* __restrict__ W3,
    const int* __restrict__ cidx, const int* __restrict__ cnt,
    __nv_bfloat16* __restrict__ qh, __nv_bfloat16* __restrict__ ql,
    __nv_bfloat16* __restrict__ kh, __nv_bfloat16* __restrict__ kl,
    __nv_bfloat16* __restrict__ vh, __nv_bfloat16* __restrict__ vl,
    __nv_bfloat16* __restrict__ h0, __nv_bfloat16* __restrict__ l0,
    __nv_bfloat16* __restrict__ h1, __nv_bfloat16* __restrict__ l1,
    __nv_bfloat16* __restrict__ h2, __nv_bfloat16* __restrict__ l2,
    __nv_bfloat16* __restrict__ h3, __nv_bfloat16* __restrict__ l3)
{
    const int sel = blockIdx.y;
    if (sel == 0) {
        int i = (blockIdx.x * 256 + threadIdx.x) * 4;
        uint32_t a, b2, c, d;
        split4(*(const float4*)(q + i), a, b2, c, d);
        *(uint32_t*)(qh + i)     = a;
        *(uint32_t*)(qh + i + 2) = b2;
        *(uint32_t*)(ql + i)     = c;
        *(uint32_t*)(ql + i + 2) = d;
    } else if (sel <= 4) {
        if (blockIdx.x >= 1024) return;
        const int w = sel - 1;
        const float* in = (w == 0) ? W0 : (w == 1) ? W1 : (w == 2) ? W2 : W3;
        __nv_bfloat16* hi = (w == 0) ? h0 : (w == 1) ? h1 : (w == 2) ? h2 : h3;
        __nv_bfloat16* lo = (w == 0) ? l0 : (w == 1) ? l1 : (w == 2) ? l2 : l3;
        int i = (blockIdx.x * 256 + threadIdx.x) * 4;
        uint32_t a, b2, c, d;
        split4(*(const float4*)(in + i), a, b2, c, d);
        *(uint32_t*)(hi + i)     = a;
        *(uint32_t*)(hi + i + 2) = b2;
        *(uint32_t*)(lo + i)     = c;
        *(uint32_t*)(lo + i + 2) = d;
    } else {
        const int b = blockIdx.x >> 11;
        const int i = blockIdx.x & (SS - 1);
        if (i >= __ldg(cnt + b)) return;
        const int src = __ldg(cidx + b * SS + i);
        const size_t goff = ((size_t)b * SS + src) * DD + threadIdx.x * 4;
        const size_t doff = ((size_t)b * SS + i) * DD + threadIdx.x * 4;
        uint32_t a0, a1, a2, a3;
        split4(*(const float4*)(k + goff), a0, a1, a2, a3);
        *(uint32_t*)(kh + doff)     = a0;
        *(uint32_t*)(kh + doff + 2) = a1;
        *(uint32_t*)(kl + doff)     = a2;
        *(uint32_t*)(kl + doff + 2) = a3;
        split4(*(const float4*)(v + goff), a0, a1, a2, a3);
        *(uint32_t*)(vh + doff)     = a0;
        *(uint32_t*)(vh + doff + 2) = a1;
        *(uint32_t*)(vl + doff)     = a2;
        *(uint32_t*)(vl + doff + 2) = a3;
    }
}

// ===========================================================================
// bf16x3 GEMM with cp.async double-buffer.
// OUTF: 1 = f32 (+bias), 2 = fp16 hi/lo scaled by 0.125 (+bias), 3 = fp16 hi (+bias)
// ===========================================================================
#define AP 40
#define BP 136

#define G_AH 0
#define G_AL 10240
#define G_BH 20480
#define G_BL 29184
#define G_STAGE 37888
#define G_SMEM (2 * G_STAGE)

template <int OUTF>
__device__ __forceinline__ void gemm_body16(
    const __nv_bfloat16* __restrict__ Ah_, const __nv_bfloat16* __restrict__ Al_,
    const __nv_bfloat16* __restrict__ Bh_, const __nv_bfloat16* __restrict__ Bl_,
    const float* __restrict__ bias,
    float* __restrict__ Cf,
    __half* __restrict__ Chh, __half* __restrict__ Chl,
    int M, int N, int K, int bx, int by)
{
    extern __shared__ char dsm[];
    const uint32_t sb = smem_u32(dsm);

    const int tid = threadIdx.x;
    const int wid = tid >> 5;
    const int lid = tid & 31;
    const int m0 = by * 128;
    const int n0 = bx * 128;
    const int wm = (wid & 3) * 32;
    const int wn = (wid >> 2) * 64;

    const int lrow = (lid & 7) + ((lid >> 3) & 1) * 8;
    const int lsel = (lid >> 4) * 8;

    const int arow = tid >> 1;
    const int acol = (tid & 1) * 16;
    const int bk = tid >> 3;
    const int bnb = (tid & 7) * 16;

    const __nv_bfloat16* pAh = Ah_ + (size_t)(m0 + arow) * K + acol;
    const __nv_bfloat16* pAl = Al_ + (size_t)(m0 + arow) * K + acol;
    const __nv_bfloat16* pBh = Bh_ + n0 + bnb;
    const __nv_bfloat16* pBl = Bl_ + n0 + bnb;

    const uint32_t sA_off = (uint32_t)(arow * AP + acol) * 2;
    const uint32_t sB_off = (uint32_t)(bk * BP + bnb) * 2;

    float acc[2][8][4];
#pragma unroll
    for (int i = 0; i < 2; i++)
#pragma unroll
        for (int j = 0; j < 8; j++)
#pragma unroll
            for (int r = 0; r < 4; r++) acc[i][j][r] = 0.f;

    const int nchunks = K / 32;

    {
        const uint32_t st = sb;
        cp16(st + G_AH + sA_off,      pAh);
        cp16(st + G_AH + sA_off + 16, pAh + 8);
        cp16(st + G_AL + sA_off,      pAl);
        cp16(st + G_AL + sA_off + 16, pAl + 8);
        const size_t roff = (size_t)bk * N;
        cp16(st + G_BH + sB_off,      pBh + roff);
        cp16(st + G_BH + sB_off + 16, pBh + roff + 8);
        cp16(st + G_BL + sB_off,      pBl + roff);
        cp16(st + G_BL + sB_off + 16, pBl + roff + 8);
        cp_commit();
    }

    for (int c = 0; c < nchunks; c++) {
        if (c + 1 < nchunks) {
            const uint32_t st = sb + ((c + 1) & 1) * G_STAGE;
            const int kb = (c + 1) * 32;
            cp16(st + G_AH + sA_off,      pAh + kb);
            cp16(st + G_AH + sA_off + 16, pAh + kb + 8);
            cp16(st + G_AL + sA_off,      pAl + kb);
            cp16(st + G_AL + sA_off + 16, pAl + kb + 8);
            const size_t roff = (size_t)(kb + bk) * N;
            cp16(st + G_BH + sB_off,      pBh + roff);
            cp16(st + G_BH + sB_off + 16, pBh + roff + 8);
            cp16(st + G_BL + sB_off,      pBl + roff);
            cp16(st + G_BL + sB_off + 16, pBl + roff + 8);
            cp_commit();
            cp_wait<1>();
        } else {
            cp_wait<0>();
        }
        __syncthreads();

        const uint32_t st = sb + (c & 1) * G_STAGE;
        const uint32_t aBaseH = st + G_AH, aBaseL = st + G_AL;
        const uint32_t bBaseH = st + G_BH, bBaseL = st + G_BL;

#pragma unroll
        for (int ks = 0; ks < 2; ks++) {
            const int kk = ks * 16;
            uint32_t aH[2][4], aL[2][4];
#pragma unroll
            for (int mt = 0; mt < 2; mt++) {
                uint32_t off = (uint32_t)((wm + mt * 16 + lrow) * AP + kk + lsel) * 2;
                ldm_x4(aH[mt], aBaseH + off);
                ldm_x4(aL[mt], aBaseL + off);
            }
#pragma unroll
            for (int jp = 0; jp < 4; jp++) {
                uint32_t bH[4], bL[4];
                uint32_t boff = (uint32_t)((kk + lrow) * BP + wn + jp * 16 + lsel) * 2;
                ldm_x4t(bH, bBaseH + boff);
                ldm_x4t(bL, bBaseL + boff);
#pragma unroll
                for (int nt = 0; nt < 2; nt++) {
#pragma unroll
                    for (int mt = 0; mt < 2; mt++) {
                        float* d = acc[mt][jp * 2 + nt];
                        mma16816(d, aH[mt], bH + nt * 2);
                        mma16816(d, aH[mt], bL + nt * 2);
                        mma16816(d, aL[mt], bH + nt * 2);
                    }
                }
            }
        }
        __syncthreads();
    }

#pragma unroll
    for (int mt = 0; mt < 2; mt++) {
        const int row = m0 + wm + mt * 16 + (lid >> 2);
#pragma unroll
        for (int nt8 = 0; nt8 < 8; nt8++) {
            const int col = n0 + wn + nt8 * 8 + (lid & 3) * 2;
            float b0 = __ldg(bias + col);
            float b1 = __ldg(bias + col + 1);
            float v00 = acc[mt][nt8][0] + b0, v01 = acc[mt][nt8][1] + b1;
            float v10 = acc[mt][nt8][2] + b0, v11 = acc[mt][nt8][3] + b1;
            if (OUTF == 1) {
                *(float2*)(Cf + (size_t)row * N + col)       = make_float2(v00, v01);
                *(float2*)(Cf + (size_t)(row + 8) * N + col) = make_float2(v10, v11);
            } else if (OUTF == 2) {
                v00 *= 0.125f; v01 *= 0.125f; v10 *= 0.125f; v11 *= 0.125f;
                float h00 = __half2float(__float2half_rn(v00));
                float h01 = __half2float(__float2half_rn(v01));
                float h10 = __half2float(__float2half_rn(v10));
                float h11 = __half2float(__float2half_rn(v11));
                *(uint32_t*)(Chh + (size_t)row * N + col)       = pack_h(v00, v01);
                *(uint32_t*)(Chl + (size_t)row * N + col)       = pack_h(v00 - h00, v01 - h01);
                *(uint32_t*)(Chh + (size_t)(row + 8) * N + col) = pack_h(v10, v11);
                *(uint32_t*)(Chl + (size_t)(row + 8) * N + col) = pack_h(v10 - h10, v11 - h11);
            } else {
                *(uint32_t*)(Chh + (size_t)row * N + col)       = pack_h(v00, v01);
                *(uint32_t*)(Chh + (size_t)(row + 8) * N + col) = pack_h(v10, v11);
            }
        }
    }
}

// Merged Q+K+V projections: z=0 Q (full, fp16 hi/lo out, scale folded),
// z=1 K, z=2 V (compacted-row early exit, fp16 hi out).
__global__ __launch_bounds__(256, 2) void gemm16_qkv_kernel(
    const __nv_bfloat16* QAh, const __nv_bfloat16* QAl,
    const __nv_bfloat16* KAh, const __nv_bfloat16* KAl,
    const __nv_bfloat16* VAh, const __nv_bfloat16* VAl,
    const __nv_bfloat16* WQh, const __nv_bfloat16* WQl,
    const __nv_bfloat16* WKh, const __nv_bfloat16* WKl,
    const __nv_bfloat16* WVh, const __nv_bfloat16* WVl,
    const float* bq, const float* bk, const float* bv,
    __half* QCh, __half* QCl, __half* KCh, __half* VCh,
    const int* cnt, int M, int N, int K)
{
    if (blockIdx.z == 0) {
        gemm_body16<2>(QAh, QAl, WQh, WQl, bq, nullptr, QCh, QCl, M, N, K,
                       blockIdx.x, blockIdx.y);
        return;
    }
    const int m0 = blockIdx.y * 128;
    const int b = m0 >> 11;
    if ((m0 & (SS - 1)) >= __ldg(cnt + b)) return;
    if (blockIdx.z == 1)
        gemm_body16<3>(KAh, KAl, WKh, WKl, bk, nullptr, KCh, nullptr, M, N, K,
                       blockIdx.x, blockIdx.y);
    else
        gemm_body16<3>(VAh, VAl, WVh, WVl, bv, nullptr, VCh, nullptr, M, N, K,
                       blockIdx.x, blockIdx.y);
}

__global__ __launch_bounds__(256, 2) void gemm16_f32out_kernel(
    const __nv_bfloat16* Ah_, const __nv_bfloat16* Al_,
    const __nv_bfloat16* Bh_, const __nv_bfloat16* Bl_,
    const float* bias, float* Cf, int M, int N, int K)
{
    gemm_body16<1>(Ah_, Al_, Bh_, Bl_, bias, Cf, nullptr, nullptr, M, N, K,
                   blockIdx.x, blockIdx.y);
}

// ===========================================================================
// fp16x2 flash attention over compacted K/V (R14, unchanged).
// ===========================================================================
#define QP 72
#define KVP 72

#define AT_QH 0
#define AT_QL (AT_QH + 128 * QP * 2)
#define AT_ST0 (AT_QL + 128 * QP * 2)
#define ATK 0
#define ATV (64 * KVP * 2)
#define AT_KV_STAGE (2 * 64 * KVP * 2)
#define AT_SMEM (AT_ST0 + 2 * AT_KV_STAGE)  // 73728

__global__ __launch_bounds__(256, 2) void attn_mma_kernel(
    const __half* __restrict__ Qh_, const __half* __restrict__ Ql_,
    const __half* __restrict__ Kh_, const __half* __restrict__ Vh_,
    const int* __restrict__ cnt,
    __nv_bfloat16* __restrict__ Oh_, __nv_bfloat16* __restrict__ Ol_)
{
    extern __shared__ char smem[];
    const uint32_t sb = smem_u32(smem);
    uint16_t* sQh = (uint16_t*)(smem + AT_QH);
    uint16_t* sQl = (uint16_t*)(smem + AT_QL);
    const uint32_t qhB = sb + AT_QH;
    const uint32_t qlB = sb + AT_QL;

    const int tid = threadIdx.x;
    const int wid = tid >> 5;
    const int lid = tid & 31;
    const int b = blockIdx.y >> 4;
    const int h = blockIdx.y & 15;
    const int q0 = blockIdx.x << 7;

    const int lrow = (lid & 7) + ((lid >> 3) & 1) * 8;
    const int lsel = (lid >> 4) * 8;
    const int qr = lid >> 2;
    const int qc = (lid & 3) * 2;

    const size_t headoff = (size_t)h * DKK;

    const int cntb = __ldg(cnt + b);
    const int ntiles = (cntb + 63) >> 6;

    const int kvr0 = tid >> 3;
    const int kvc0 = (tid & 7) * 8;
    const size_t kvg0 = (size_t)kvr0 * DD + kvc0;
    const size_t kvg1 = (size_t)(kvr0 + 32) * DD + kvc0;
    const uint32_t kvs0 = (uint32_t)(kvr0 * KVP + kvc0) * 2;
    const uint32_t kvs1 = (uint32_t)((kvr0 + 32) * KVP + kvc0) * 2;

    const __half* Kh0 = Kh_ + (size_t)b * SS * DD + headoff;
    const __half* Vh0 = Vh_ + (size_t)b * SS * DD + headoff;

    // ---- load Q tile (fp16 hi/lo, already scaled) ----
    {
        const __half* Qbh = Qh_ + ((size_t)b * SS + q0) * DD + headoff;
        const __half* Qbl = Ql_ + ((size_t)b * SS + q0) * DD + headoff;
#pragma unroll
        for (int p = 0; p < 4; p++) {
            int u = tid + p * 256;
            int r = u >> 3;
            int c8 = (u & 7) * 8;
            *(uint4*)(sQh + r * QP + c8) = *(const uint4*)(Qbh + (size_t)r * DD + c8);
            *(uint4*)(sQl + r * QP + c8) = *(const uint4*)(Qbl + (size_t)r * DD + c8);
        }
    }

    // ---- prefetch tile 0 ----
    {
        const uint32_t st = sb + AT_ST0;
        cp16(st + ATK + kvs0, Kh0 + kvg0);
        cp16(st + ATK + kvs1, Kh0 + kvg1);
        cp16(st + ATV + kvs0, Vh0 + kvg0);
        cp16(st + ATV + kvs1, Vh0 + kvg1);
        cp_commit();
    }

    float o[8][4];
#pragma unroll
    for (int j = 0; j < 8; j++)
#pragma unroll
        for (int r = 0; r < 4; r++) o[j][r] = 0.f;
    float m0v = -3.0e38f, m1v = -3.0e38f, l0v = 0.f, l1v = 0.f;

    for (int kt = 0; kt < ntiles; kt++) {
        const int kv0 = kt * 64;
        if (kt + 1 < ntiles) {
            const uint32_t st = sb + AT_ST0 + ((kt + 1) & 1) * AT_KV_STAGE;
            const size_t gb = (size_t)(kv0 + 64) * DD;
            cp16(st + ATK + kvs0, Kh0 + gb + kvg0);
            cp16(st + ATK + kvs1, Kh0 + gb + kvg1);
            cp16(st + ATV + kvs0, Vh0 + gb + kvg0);
            cp16(st + ATV + kvs1, Vh0 + gb + kvg1);
            cp_commit();
            cp_wait<1>();
        } else {
            cp_wait<0>();
        }
        __syncthreads();

        const uint32_t st = sb + AT_ST0 + (kt & 1) * AT_KV_STAGE;
        const uint32_t khB = st + ATK;
        const uint32_t vhB = st + ATV;

        // ---- S = (Qh + Ql) @ Kh^T (fp16x2) ----
        float s[8][4];
#pragma unroll
        for (int j = 0; j < 8; j++)
#pragma unroll
            for (int r = 0; r < 4; r++) s[j][r] = 0.f;

#pragma unroll
        for (int k = 0; k < 4; k++) {
            uint32_t qh[4], ql[4];
            uint32_t qoff = (uint32_t)((wid * 16 + lrow) * QP + k * 16 + lsel) * 2;
            ldm_x4(qh, qhB + qoff);
            ldm_x4(ql, qlB + qoff);
#pragma unroll
            for (int nb = 0; nb < 4; nb++) {
                uint32_t kh[4];
                uint32_t koff = (uint32_t)((nb * 16 + lrow) * KVP + k * 16 + lsel) * 2;
                ldm_x4(kh, khB + koff);
                uint32_t b0[2] = {kh[0], kh[2]}, b1[2] = {kh[1], kh[3]};
                mma16816h(s[nb * 2], qh, b0);
                mma16816h(s[nb * 2], ql, b0);
                mma16816h(s[nb * 2 + 1], qh, b1);
                mma16816h(s[nb * 2 + 1], ql, b1);
            }
        }

        // ---- padding mask ----
#pragma unroll
        for (int j = 0; j < 8; j++) {
            int col0 = kv0 + j * 8 + qc;
            float mk0 = (col0 < cntb) ? 0.f : -1.0e10f;
            float mk1 = (col0 + 1 < cntb) ? 0.f : -1.0e10f;
            s[j][0] += mk0; s[j][1] += mk1;
            s[j][2] += mk0; s[j][3] += mk1;
        }

        // ---- warp-local online softmax ----
        float mt0 = -3.0e38f, mt1 = -3.0e38f;
#pragma unroll
        for (int j = 0; j < 8; j++) {
            mt0 = fmaxf(mt0, fmaxf(s[j][0], s[j][1]));
            mt1 = fmaxf(mt1, fmaxf(s[j][2], s[j][3]));
        }
        mt0 = fmaxf(mt0, __shfl_xor_sync(0xFFFFFFFF, mt0, 1));
        mt0 = fmaxf(mt0, __shfl_xor_sync(0xFFFFFFFF, mt0, 2));
        mt1 = fmaxf(mt1, __shfl_xor_sync(0xFFFFFFFF, mt1, 1));
        mt1 = fmaxf(mt1, __shfl_xor_sync(0xFFFFFFFF, mt1, 2));

        float mn0 = fmaxf(m0v, mt0), mn1 = fmaxf(m1v, mt1);
        float corr0 = __expf(m0v - mn0), corr1 = __expf(m1v - mn1);
        m0v = mn0; m1v = mn1;

        float ts0 = 0.f, ts1 = 0.f;
#pragma unroll
        for (int j = 0; j < 8; j++) {
            s[j][0] = __expf(s[j][0] - mn0);
            s[j][1] = __expf(s[j][1] - mn0);
            s[j][2] = __expf(s[j][2] - mn1);
            s[j][3] = __expf(s[j][3] - mn1);
            ts0 += s[j][0] + s[j][1];
            ts1 += s[j][2] + s[j][3];
        }
        ts0 += __shfl_xor_sync(0xFFFFFFFF, ts0, 1);
        ts0 += __shfl_xor_sync(0xFFFFFFFF, ts0, 2);
        ts1 += __shfl_xor_sync(0xFFFFFFFF, ts1, 1);
        ts1 += __shfl_xor_sync(0xFFFFFFFF, ts1, 2);
        l0v = l0v * corr0 + ts0;
        l1v = l1v * corr1 + ts1;

#pragma unroll
        for (int j = 0; j < 8; j++) {
            o[j][0] *= corr0; o[j][1] *= corr0;
            o[j][2] *= corr1; o[j][3] *= corr1;
        }

        // ---- O += (Ph + Pl) @ Vh (fp16x2) ----
#pragma unroll
        for (int t = 0; t < 4; t++) {
            uint32_t pah[4], pal[4];
            {
                float p00 = s[2 * t][0],     p01 = s[2 * t][1];
                float p10 = s[2 * t][2],     p11 = s[2 * t][3];
                float p20 = s[2 * t + 1][0], p21 = s[2 * t + 1][1];
                float p30 = s[2 * t + 1][2], p31 = s[2 * t + 1][3];
                pah[0] = pack_h(p00, p01);
                pah[1] = pack_h(p10, p11);
                pah[2] = pack_h(p20, p21);
                pah[3] = pack_h(p30, p31);
                __half2* hb;
                hb = (__half2*)&pah[0];
                pal[0] = pack_h(p00 - __half2float(hb->x), p01 - __half2float(hb->y));
                hb = (__half2*)&pah[1];
                pal[1] = pack_h(p10 - __half2float(hb->x), p11 - __half2float(hb->y));
                hb = (__half2*)&pah[2];
                pal[2] = pack_h(p20 - __half2float(hb->x), p21 - __half2float(hb->y));
                hb = (__half2*)&pah[3];
                pal[3] = pack_h(p30 - __half2float(hb->x), p31 - __half2float(hb->y));
            }
#pragma unroll
            for (int nb = 0; nb < 4; nb++) {
                uint32_t vh[4];
                uint32_t voff = (uint32_t)((t * 16 + lrow) * KVP + nb * 16 + lsel) * 2;
                ldm_x4t(vh, vhB + voff);
                mma16816h(o[nb * 2], pah, vh);
                mma16816h(o[nb * 2], pal, vh);
                mma16816h(o[nb * 2 + 1], pah, vh + 2);
                mma16816h(o[nb * 2 + 1], pal, vh + 2);
            }
        }
        __syncthreads();
    }

    // ---- epilogue: normalize, split bf16 hi/lo for out-proj ----
    float inv0 = 1.f / l0v, inv1 = 1.f / l1v;
    const int r0g = q0 + wid * 16 + qr;
#pragma unroll
    for (int j = 0; j < 8; j++) {
        const size_t col = headoff + j * 8 + qc;
        float v00 = o[j][0] * inv0, v01 = o[j][1] * inv0;
        float v10 = o[j][2] * inv1, v11 = o[j][3] * inv1;
        __nv_bfloat162 h0 = __floats2bfloat162_rn(v00, v01);
        __nv_bfloat162 l0 = __floats2bfloat162_rn(v00 - __bfloat162float(h0.x),
                                                  v01 - __bfloat162float(h0.y));
        __nv_bfloat162 h1 = __floats2bfloat162_rn(v10, v11);
        __nv_bfloat162 l1 = __floats2bfloat162_rn(v10 - __bfloat162float(h1.x),
                                                  v11 - __bfloat162float(h1.y));
        *(__nv_bfloat162*)(Oh_ + ((size_t)b * SS + r0g) * DD + col)     = h0;
        *(__nv_bfloat162*)(Ol_ + ((size_t)b * SS + r0g) * DD + col)     = l0;
        *(__nv_bfloat162*)(Oh_ + ((size_t)b * SS + r0g + 8) * DD + col) = h1;
        *(__nv_bfloat162*)(Ol_ + ((size_t)b * SS + r0g + 8) * DD + col) = l1;
    }
}

// ---------------------------------------------------------------------------
extern "C" void kernel_launch(void* const* d_in, const int* in_sizes, int n_in,
                              void* d_out, int out_size)
{
    const float* q    = (const float*)d_in[0];
    const float* k    = (const float*)d_in[1];
    const float* v    = (const float*)d_in[2];
    const int*   mask = (const int*)d_in[3];
    const float* Wq   = (const float*)d_in[4];
    const float* bq   = (const float*)d_in[5];
    const float* Wk   = (const float*)d_in[6];
    const float* bk   = (const float*)d_in[7];
    const float* Wv   = (const float*)d_in[8];
    const float* bv   = (const float*)d_in[9];
    const float* Wo   = (const float*)d_in[10];
    const float* bo   = (const float*)d_in[11];
    float* out = (float*)d_out;

    __nv_bfloat16 *qh, *ql, *kch, *kcl, *vch, *vcl;
    __nv_bfloat16 *wqh, *wql, *wkh, *wkl, *wvh, *wvl, *woh, *wol;
    __nv_bfloat16 *ah, *al;
    __half *qph, *qpl, *kph, *vph;
    int *cidx, *cnt;
    cudaGetSymbolAddress((void**)&qh, g_qh);     cudaGetSymbolAddress((void**)&ql, g_ql);
    cudaGetSymbolAddress((void**)&kch, g_kc_h);  cudaGetSymbolAddress((void**)&kcl, g_kc_l);
    cudaGetSymbolAddress((void**)&vch, g_vc_h);  cudaGetSymbolAddress((void**)&vcl, g_vc_l);
    cudaGetSymbolAddress((void**)&wqh, g_wqh);   cudaGetSymbolAddress((void**)&wql, g_wql);
    cudaGetSymbolAddress((void**)&wkh, g_wkh);   cudaGetSymbolAddress((void**)&wkl, g_wkl);
    cudaGetSymbolAddress((void**)&wvh, g_wvh);   cudaGetSymbolAddress((void**)&wvl, g_wvl);
    cudaGetSymbolAddress((void**)&woh, g_woh);   cudaGetSymbolAddress((void**)&wol, g_wol);
    cudaGetSymbolAddress((void**)&qph, g_qph);   cudaGetSymbolAddress((void**)&qpl, g_qpl);
    cudaGetSymbolAddress((void**)&kph, g_kph);
    cudaGetSymbolAddress((void**)&vph, g_vph);
    cudaGetSymbolAddress((void**)&ah, g_ah);     cudaGetSymbolAddress((void**)&al, g_al);
    cudaGetSymbolAddress((void**)&cidx, g_cidx);
    cudaGetSymbolAddress((void**)&cnt, g_cnt);

    cudaFuncSetAttribute(gemm16_qkv_kernel,
                         cudaFuncAttributeMaxDynamicSharedMemorySize, G_SMEM);
    cudaFuncSetAttribute(gemm16_f32out_kernel,
                         cudaFuncAttributeMaxDynamicSharedMemorySize, G_SMEM);
    cudaFuncSetAttribute(attn_mma_kernel,
                         cudaFuncAttributeMaxDynamicSharedMemorySize, AT_SMEM);

    compact_kernel<<<BB, 256>>>(mask, cidx, cnt);
    split_all_kernel<<<dim3(4096, 6), 256>>>(q, k, v, Wq, Wk, Wv, Wo, cidx, cnt,
                                             qh, ql, kch, kcl, vch, vcl,
                                             wqh, wql, wkh, wkl,
                                             wvh, wvl, woh, wol);

    gemm16_qkv_kernel<<<dim3(8, 32, 3), 256, G_SMEM>>>(
        qh, ql, kch, kcl, vch, vcl,
        wqh, wql, wkh, wkl, wvh, wvl,
        bq, bk, bv,
        qph, qpl, kph, vph,
        cnt, BB * SS, DD, DD);

    attn_mma_kernel<<<dim3(SS / 128, BB * HH), 256, AT_SMEM>>>(
        qph, qpl, kph, vph, cnt, ah, al);

    dim3 gb(DD / 128, (BB * SS) / 128);
    gemm16_f32out_kernel<<<gb, 256, G_SMEM>>>(ah, al, woh, wol, bo, out, BB * SS, DD, DD);
}

// round 17
// speedup vs baseline: 1.3581x; 1.0542x over previous
#include <cuda_runtime.h>
#include <cuda_bf16.h>
#include <cuda_fp16.h>
#include <math.h>
#include <cstdint>

#define BB 2
#define SS 2048
#define DD 1024
#define HH 16
#define DKK 64

// ---- scratch (allocation-free rule: __device__ globals) ----
__device__ __nv_bfloat16 g_qh[BB * SS * DD], g_ql[BB * SS * DD];
__device__ __nv_bfloat16 g_kc_h[BB * SS * DD], g_kc_l[BB * SS * DD];
__device__ __nv_bfloat16 g_vc_h[BB * SS * DD], g_vc_l[BB * SS * DD];
__device__ __nv_bfloat16 g_wqh[DD * DD], g_wql[DD * DD];
__device__ __nv_bfloat16 g_wkh[DD * DD], g_wkl[DD * DD];
__device__ __nv_bfloat16 g_wvh[DD * DD], g_wvl[DD * DD];
__device__ __nv_bfloat16 g_woh[DD * DD], g_wol[DD * DD];
__device__ __half g_qph[BB * SS * DD], g_qpl[BB * SS * DD];   // Q proj fp16 hi/lo (pre-scaled)
__device__ __half g_kph[BB * SS * DD];                         // K proj fp16 hi only
__device__ __half g_vph[BB * SS * DD];                         // V proj fp16 hi only
__device__ __nv_bfloat16 g_ah[BB * SS * DD], g_al[BB * SS * DD];
__device__ int g_cidx[BB * SS];
__device__ int g_cnt[BB];

// ===========================================================================
// helpers
// ===========================================================================
__device__ __forceinline__ uint32_t smem_u32(const void* p) {
    uint32_t a;
    asm("{ .reg .u64 t; cvta.to.shared.u64 t, %1; cvt.u32.u64 %0, t; }"
        : "=r"(a) : "l"(p));
    return a;
}
__device__ __forceinline__ void ldm_x4(uint32_t* r, uint32_t addr) {
    asm volatile("ldmatrix.sync.aligned.m8n8.x4.shared.b16 {%0,%1,%2,%3}, [%4];"
                 : "=r"(r[0]), "=r"(r[1]), "=r"(r[2]), "=r"(r[3]) : "r"(addr));
}
__device__ __forceinline__ void ldm_x4t(uint32_t* r, uint32_t addr) {
    asm volatile("ldmatrix.sync.aligned.m8n8.x4.trans.shared.b16 {%0,%1,%2,%3}, [%4];"
                 : "=r"(r[0]), "=r"(r[1]), "=r"(r[2]), "=r"(r[3]) : "r"(addr));
}
// bf16 MMA
__device__ __forceinline__ void mma16816(float* d, const uint32_t* a, const uint32_t* b) {
    asm volatile(
        "mma.sync.aligned.m16n8k16.row.col.f32.bf16.bf16.f32 "
        "{%0,%1,%2,%3}, {%4,%5,%6,%7}, {%8,%9}, {%0,%1,%2,%3};"
        : "+f"(d[0]), "+f"(d[1]), "+f"(d[2]), "+f"(d[3])
        : "r"(a[0]), "r"(a[1]), "r"(a[2]), "r"(a[3]), "r"(b[0]), "r"(b[1]));
}
// fp16 MMA
__device__ __forceinline__ void mma16816h(float* d, const uint32_t* a, const uint32_t* b) {
    asm volatile(
        "mma.sync.aligned.m16n8k16.row.col.f32.f16.f16.f32 "
        "{%0,%1,%2,%3}, {%4,%5,%6,%7}, {%8,%9}, {%0,%1,%2,%3};"
        : "+f"(d[0]), "+f"(d[1]), "+f"(d[2]), "+f"(d[3])
        : "r"(a[0]), "r"(a[1]), "r"(a[2]), "r"(a[3]), "r"(b[0]), "r"(b[1]));
}
__device__ __forceinline__ uint32_t pack_h(float x, float y) {
    __half2 t = __floats2half2_rn(x, y);
    return *(uint32_t*)&t;
}
__device__ __forceinline__ void cp16(uint32_t s, const void* g) {
    asm volatile("cp.async.cg.shared.global [%0], [%1], 16;" :: "r"(s), "l"(g));
}
__device__ __forceinline__ void cp_commit() {
    asm volatile("cp.async.commit_group;" ::: "memory");
}
template <int N>
__device__ __forceinline__ void cp_wait() {
    asm volatile("cp.async.wait_group %0;" :: "n"(N) : "memory");
}
__device__ __forceinline__ void split4(float4 v, uint32_t& h01, uint32_t& h23,
                                       uint32_t& l01, uint32_t& l23) {
    __nv_bfloat162 h0 = __floats2bfloat162_rn(v.x, v.y);
    __nv_bfloat162 h1 = __floats2bfloat162_rn(v.z, v.w);
    __nv_bfloat162 l0 = __floats2bfloat162_rn(v.x - __bfloat162float(h0.x),
                                              v.y - __bfloat162float(h0.y));
    __nv_bfloat162 l1 = __floats2bfloat162_rn(v.z - __bfloat162float(h1.x),
                                              v.w - __bfloat162float(h1.y));
    h01 = *(uint32_t*)&h0; h23 = *(uint32_t*)&h1;
    l01 = *(uint32_t*)&l0; l23 = *(uint32_t*)&l1;
}

// ===========================================================================
// mask compaction
// ===========================================================================
__global__ __launch_bounds__(256) void compact_kernel(
    const int* __restrict__ mask, int* __restrict__ cidx, int* __restrict__ cnt)
{
    const int b = blockIdx.x;
    const int t = threadIdx.x;
    const int* mb = mask + b * SS;
    int keep[8];
    int c = 0;
#pragma unroll
    for (int e = 0; e < 8; e++) {
        int p = t * 8 + e;
        if (mb[p] == 0) keep[c++] = p;
    }
    __shared__ int sc[256];
    sc[t] = c;
    __syncthreads();
    for (int off = 1; off < 256; off <<= 1) {
        int v = sc[t];
        int add = (t >= off) ? sc[t - off] : 0;
        __syncthreads();
        sc[t] = v + add;
        __syncthreads();
    }
    int ofs = sc[t] - c;
    int* out = cidx + b * SS;
    for (int i = 0; i < c; i++) out[ofs + i] = keep[i];
    if (t == 255) cnt[b] = sc[255];
}

// ===========================================================================
// Fused prep: q split (y=0), weight splits (y=1..4), K/V gather-split (y=5)
// ===========================================================================
__global__ __launch_bounds__(256) void split_all_kernel(
    const float* __restrict__ q, const float* __restrict__ k,
    const float* __restrict__ v,
    const float* __restrict__ W0, const float* __restrict__ W1,
    const float* __restrict__ W2, const float* __restrict__ W3,
    const int* __restrict__ cidx, const int* __restrict__ cnt,
    __nv_bfloat16* __restrict__ qh, __nv_bfloat16* __restrict__ ql,
    __nv_bfloat16* __restrict__ kh, __nv_bfloat16* __restrict__ kl,
    __nv_bfloat16* __restrict__ vh, __nv_bfloat16* __restrict__ vl,
    __nv_bfloat16* __restrict__ h0, __nv_bfloat16* __restrict__ l0,
    __nv_bfloat16* __restrict__ h1, __nv_bfloat16* __restrict__ l1,
    __nv_bfloat16* __restrict__ h2, __nv_bfloat16* __restrict__ l2,
    __nv_bfloat16* __restrict__ h3, __nv_bfloat16* __restrict__ l3)
{
    const int sel = blockIdx.y;
    if (sel == 0) {
        int i = (blockIdx.x * 256 + threadIdx.x) * 4;
        uint32_t a, b2, c, d;
        split4(*(const float4*)(q + i), a, b2, c, d);
        *(uint32_t*)(qh + i)     = a;
        *(uint32_t*)(qh + i + 2) = b2;
        *(uint32_t*)(ql + i)     = c;
        *(uint32_t*)(ql + i + 2) = d;
    } else if (sel <= 4) {
        if (blockIdx.x >= 1024) return;
        const int w = sel - 1;
        const float* in = (w == 0) ? W0 : (w == 1) ? W1 : (w == 2) ? W2 : W3;
        __nv_bfloat16* hi = (w == 0) ? h0 : (w == 1) ? h1 : (w == 2) ? h2 : h3;
        __nv_bfloat16* lo = (w == 0) ? l0 : (w == 1) ? l1 : (w == 2) ? l2 : l3;
        int i = (blockIdx.x * 256 + threadIdx.x) * 4;
        uint32_t a, b2, c, d;
        split4(*(const float4*)(in + i), a, b2, c, d);
        *(uint32_t*)(hi + i)     = a;
        *(uint32_t*)(hi + i + 2) = b2;
        *(uint32_t*)(lo + i)     = c;
        *(uint32_t*)(lo + i + 2) = d;
    } else {
        const int b = blockIdx.x >> 11;
        const int i = blockIdx.x & (SS - 1);
        if (i >= __ldg(cnt + b)) return;
        const int src = __ldg(cidx + b * SS + i);
        const size_t goff = ((size_t)b * SS + src) * DD + threadIdx.x * 4;
        const size_t doff = ((size_t)b * SS + i) * DD + threadIdx.x * 4;
        uint32_t a0, a1, a2, a3;
        split4(*(const float4*)(k + goff), a0, a1, a2, a3);
        *(uint32_t*)(kh + doff)     = a0;
        *(uint32_t*)(kh + doff + 2) = a1;
        *(uint32_t*)(kl + doff)     = a2;
        *(uint32_t*)(kl + doff + 2) = a3;
        split4(*(const float4*)(v + goff), a0, a1, a2, a3);
        *(uint32_t*)(vh + doff)     = a0;
        *(uint32_t*)(vh + doff + 2) = a1;
        *(uint32_t*)(vl + doff)     = a2;
        *(uint32_t*)(vl + doff + 2) = a3;
    }
}

// ===========================================================================
// bf16x3 GEMM with cp.async double-buffer.
// OUTF: 1 = f32 (+bias), 2 = fp16 hi/lo scaled by 0.125 (+bias), 3 = fp16 hi (+bias)
// ===========================================================================
#define AP 40
#define BP 136

#define G_AH 0
#define G_AL 10240
#define G_BH 20480
#define G_BL 29184
#define G_STAGE 37888
#define G_SMEM (2 * G_STAGE)

template <int OUTF>
__device__ __forceinline__ void gemm_body16(
    const __nv_bfloat16* __restrict__ Ah_, const __nv_bfloat16* __restrict__ Al_,
    const __nv_bfloat16* __restrict__ Bh_, const __nv_bfloat16* __restrict__ Bl_,
    const float* __restrict__ bias,
    float* __restrict__ Cf,
    __half* __restrict__ Chh, __half* __restrict__ Chl,
    int M, int N, int K, int bx, int by)
{
    extern __shared__ char dsm[];
    const uint32_t sb = smem_u32(dsm);

    const int tid = threadIdx.x;
    const int wid = tid >> 5;
    const int lid = tid & 31;
    const int m0 = by * 128;
    const int n0 = bx * 128;
    const int wm = (wid & 3) * 32;
    const int wn = (wid >> 2) * 64;

    const int lrow = (lid & 7) + ((lid >> 3) & 1) * 8;
    const int lsel = (lid >> 4) * 8;

    const int arow = tid >> 1;
    const int acol = (tid & 1) * 16;
    const int bk = tid >> 3;
    const int bnb = (tid & 7) * 16;

    const __nv_bfloat16* pAh = Ah_ + (size_t)(m0 + arow) * K + acol;
    const __nv_bfloat16* pAl = Al_ + (size_t)(m0 + arow) * K + acol;
    const __nv_bfloat16* pBh = Bh_ + n0 + bnb;
    const __nv_bfloat16* pBl = Bl_ + n0 + bnb;

    const uint32_t sA_off = (uint32_t)(arow * AP + acol) * 2;
    const uint32_t sB_off = (uint32_t)(bk * BP + bnb) * 2;

    float acc[2][8][4];
#pragma unroll
    for (int i = 0; i < 2; i++)
#pragma unroll
        for (int j = 0; j < 8; j++)
#pragma unroll
            for (int r = 0; r < 4; r++) acc[i][j][r] = 0.f;

    const int nchunks = K / 32;

    {
        const uint32_t st = sb;
        cp16(st + G_AH + sA_off,      pAh);
        cp16(st + G_AH + sA_off + 16, pAh + 8);
        cp16(st + G_AL + sA_off,      pAl);
        cp16(st + G_AL + sA_off + 16, pAl + 8);
        const size_t roff = (size_t)bk * N;
        cp16(st + G_BH + sB_off,      pBh + roff);
        cp16(st + G_BH + sB_off + 16, pBh + roff + 8);
        cp16(st + G_BL + sB_off,      pBl + roff);
        cp16(st + G_BL + sB_off + 16, pBl + roff + 8);
        cp_commit();
    }

    for (int c = 0; c < nchunks; c++) {
        if (c + 1 < nchunks) {
            const uint32_t st = sb + ((c + 1) & 1) * G_STAGE;
            const int kb = (c + 1) * 32;
            cp16(st + G_AH + sA_off,      pAh + kb);
            cp16(st + G_AH + sA_off + 16, pAh + kb + 8);
            cp16(st + G_AL + sA_off,      pAl + kb);
            cp16(st + G_AL + sA_off + 16, pAl + kb + 8);
            const size_t roff = (size_t)(kb + bk) * N;
            cp16(st + G_BH + sB_off,      pBh + roff);
            cp16(st + G_BH + sB_off + 16, pBh + roff + 8);
            cp16(st + G_BL + sB_off,      pBl + roff);
            cp16(st + G_BL + sB_off + 16, pBl + roff + 8);
            cp_commit();
            cp_wait<1>();
        } else {
            cp_wait<0>();
        }
        __syncthreads();

        const uint32_t st = sb + (c & 1) * G_STAGE;
        const uint32_t aBaseH = st + G_AH, aBaseL = st + G_AL;
        const uint32_t bBaseH = st + G_BH, bBaseL = st + G_BL;

#pragma unroll
        for (int ks = 0; ks < 2; ks++) {
            const int kk = ks * 16;
            uint32_t aH[2][4], aL[2][4];
#pragma unroll
            for (int mt = 0; mt < 2; mt++) {
                uint32_t off = (uint32_t)((wm + mt * 16 + lrow) * AP + kk + lsel) * 2;
                ldm_x4(aH[mt], aBaseH + off);
                ldm_x4(aL[mt], aBaseL + off);
            }
#pragma unroll
            for (int jp = 0; jp < 4; jp++) {
                uint32_t bH[4], bL[4];
                uint32_t boff = (uint32_t)((kk + lrow) * BP + wn + jp * 16 + lsel) * 2;
                ldm_x4t(bH, bBaseH + boff);
                ldm_x4t(bL, bBaseL + boff);
#pragma unroll
                for (int nt = 0; nt < 2; nt++) {
#pragma unroll
                    for (int mt = 0; mt < 2; mt++) {
                        float* d = acc[mt][jp * 2 + nt];
                        mma16816(d, aH[mt], bH + nt * 2);
                        mma16816(d, aH[mt], bL + nt * 2);
                        mma16816(d, aL[mt], bH + nt * 2);
                    }
                }
            }
        }
        __syncthreads();
    }

#pragma unroll
    for (int mt = 0; mt < 2; mt++) {
        const int row = m0 + wm + mt * 16 + (lid >> 2);
#pragma unroll
        for (int nt8 = 0; nt8 < 8; nt8++) {
            const int col = n0 + wn + nt8 * 8 + (lid & 3) * 2;
            float b0 = __ldg(bias + col);
            float b1 = __ldg(bias + col + 1);
            float v00 = acc[mt][nt8][0] + b0, v01 = acc[mt][nt8][1] + b1;
            float v10 = acc[mt][nt8][2] + b0, v11 = acc[mt][nt8][3] + b1;
            if (OUTF == 1) {
                *(float2*)(Cf + (size_t)row * N + col)       = make_float2(v00, v01);
                *(float2*)(Cf + (size_t)(row + 8) * N + col) = make_float2(v10, v11);
            } else if (OUTF == 2) {
                v00 *= 0.125f; v01 *= 0.125f; v10 *= 0.125f; v11 *= 0.125f;
                float h00 = __half2float(__float2half_rn(v00));
                float h01 = __half2float(__float2half_rn(v01));
                float h10 = __half2float(__float2half_rn(v10));
                float h11 = __half2float(__float2half_rn(v11));
                *(uint32_t*)(Chh + (size_t)row * N + col)       = pack_h(v00, v01);
                *(uint32_t*)(Chl + (size_t)row * N + col)       = pack_h(v00 - h00, v01 - h01);
                *(uint32_t*)(Chh + (size_t)(row + 8) * N + col) = pack_h(v10, v11);
                *(uint32_t*)(Chl + (size_t)(row + 8) * N + col) = pack_h(v10 - h10, v11 - h11);
            } else {
                *(uint32_t*)(Chh + (size_t)row * N + col)       = pack_h(v00, v01);
                *(uint32_t*)(Chh + (size_t)(row + 8) * N + col) = pack_h(v10, v11);
            }
        }
    }
}

// Merged Q+K+V projections: z=0 Q (full, fp16 hi/lo out, scale folded),
// z=1 K, z=2 V (compacted-row early exit, fp16 hi out).
__global__ __launch_bounds__(256, 2) void gemm16_qkv_kernel(
    const __nv_bfloat16* QAh, const __nv_bfloat16* QAl,
    const __nv_bfloat16* KAh, const __nv_bfloat16* KAl,
    const __nv_bfloat16* VAh, const __nv_bfloat16* VAl,
    const __nv_bfloat16* WQh, const __nv_bfloat16* WQl,
    const __nv_bfloat16* WKh, const __nv_bfloat16* WKl,
    const __nv_bfloat16* WVh, const __nv_bfloat16* WVl,
    const float* bq, const float* bk, const float* bv,
    __half* QCh, __half* QCl, __half* KCh, __half* VCh,
    const int* cnt, int M, int N, int K)
{
    if (blockIdx.z == 0) {
        gemm_body16<2>(QAh, QAl, WQh, WQl, bq, nullptr, QCh, QCl, M, N, K,
                       blockIdx.x, blockIdx.y);
        return;
    }
    const int m0 = blockIdx.y * 128;
    const int b = m0 >> 11;
    if ((m0 & (SS - 1)) >= __ldg(cnt + b)) return;
    if (blockIdx.z == 1)
        gemm_body16<3>(KAh, KAl, WKh, WKl, bk, nullptr, KCh, nullptr, M, N, K,
                       blockIdx.x, blockIdx.y);
    else
        gemm_body16<3>(VAh, VAl, WVh, WVl, bv, nullptr, VCh, nullptr, M, N, K,
                       blockIdx.x, blockIdx.y);
}

__global__ __launch_bounds__(256, 2) void gemm16_f32out_kernel(
    const __nv_bfloat16* Ah_, const __nv_bfloat16* Al_,
    const __nv_bfloat16* Bh_, const __nv_bfloat16* Bl_,
    const float* bias, float* Cf, int M, int N, int K)
{
    gemm_body16<1>(Ah_, Al_, Bh_, Bl_, bias, Cf, nullptr, nullptr, M, N, K,
                   blockIdx.x, blockIdx.y);
}

// ===========================================================================
// fp16 flash attention over compacted K/V.
// S = (Qh+Ql)·Kh (2 MMAs/frag); O = Ph·Vh (1 MMA/frag, P truncated to fp16 —
// P in [0,1] so truncation error ~2^-11 relative, within budget).
// ===========================================================================
#define QP 72
#define KVP 72

#define AT_QH 0
#define AT_QL (AT_QH + 128 * QP * 2)
#define AT_ST0 (AT_QL + 128 * QP * 2)
#define ATK 0
#define ATV (64 * KVP * 2)
#define AT_KV_STAGE (2 * 64 * KVP * 2)
#define AT_SMEM (AT_ST0 + 2 * AT_KV_STAGE)  // 73728

__global__ __launch_bounds__(256, 2) void attn_mma_kernel(
    const __half* __restrict__ Qh_, const __half* __restrict__ Ql_,
    const __half* __restrict__ Kh_, const __half* __restrict__ Vh_,
    const int* __restrict__ cnt,
    __nv_bfloat16* __restrict__ Oh_, __nv_bfloat16* __restrict__ Ol_)
{
    extern __shared__ char smem[];
    const uint32_t sb = smem_u32(smem);
    uint16_t* sQh = (uint16_t*)(smem + AT_QH);
    uint16_t* sQl = (uint16_t*)(smem + AT_QL);
    const uint32_t qhB = sb + AT_QH;
    const uint32_t qlB = sb + AT_QL;

    const int tid = threadIdx.x;
    const int wid = tid >> 5;
    const int lid = tid & 31;
    const int b = blockIdx.y >> 4;
    const int h = blockIdx.y & 15;
    const int q0 = blockIdx.x << 7;

    const int lrow = (lid & 7) + ((lid >> 3) & 1) * 8;
    const int lsel = (lid >> 4) * 8;
    const int qr = lid >> 2;
    const int qc = (lid & 3) * 2;

    const size_t headoff = (size_t)h * DKK;

    const int cntb = __ldg(cnt + b);
    const int ntiles = (cntb + 63) >> 6;

    const int kvr0 = tid >> 3;
    const int kvc0 = (tid & 7) * 8;
    const size_t kvg0 = (size_t)kvr0 * DD + kvc0;
    const size_t kvg1 = (size_t)(kvr0 + 32) * DD + kvc0;
    const uint32_t kvs0 = (uint32_t)(kvr0 * KVP + kvc0) * 2;
    const uint32_t kvs1 = (uint32_t)((kvr0 + 32) * KVP + kvc0) * 2;

    const __half* Kh0 = Kh_ + (size_t)b * SS * DD + headoff;
    const __half* Vh0 = Vh_ + (size_t)b * SS * DD + headoff;

    // ---- load Q tile (fp16 hi/lo, already scaled) ----
    {
        const __half* Qbh = Qh_ + ((size_t)b * SS + q0) * DD + headoff;
        const __half* Qbl = Ql_ + ((size_t)b * SS + q0) * DD + headoff;
#pragma unroll
        for (int p = 0; p < 4; p++) {
            int u = tid + p * 256;
            int r = u >> 3;
            int c8 = (u & 7) * 8;
            *(uint4*)(sQh + r * QP + c8) = *(const uint4*)(Qbh + (size_t)r * DD + c8);
            *(uint4*)(sQl + r * QP + c8) = *(const uint4*)(Qbl + (size_t)r * DD + c8);
        }
    }

    // ---- prefetch tile 0 ----
    {
        const uint32_t st = sb + AT_ST0;
        cp16(st + ATK + kvs0, Kh0 + kvg0);
        cp16(st + ATK + kvs1, Kh0 + kvg1);
        cp16(st + ATV + kvs0, Vh0 + kvg0);
        cp16(st + ATV + kvs1, Vh0 + kvg1);
        cp_commit();
    }

    float o[8][4];
#pragma unroll
    for (int j = 0; j < 8; j++)
#pragma unroll
        for (int r = 0; r < 4; r++) o[j][r] = 0.f;
    float m0v = -3.0e38f, m1v = -3.0e38f, l0v = 0.f, l1v = 0.f;

    for (int kt = 0; kt < ntiles; kt++) {
        const int kv0 = kt * 64;
        if (kt + 1 < ntiles) {
            const uint32_t st = sb + AT_ST0 + ((kt + 1) & 1) * AT_KV_STAGE;
            const size_t gb = (size_t)(kv0 + 64) * DD;
            cp16(st + ATK + kvs0, Kh0 + gb + kvg0);
            cp16(st + ATK + kvs1, Kh0 + gb + kvg1);
            cp16(st + ATV + kvs0, Vh0 + gb + kvg0);
            cp16(st + ATV + kvs1, Vh0 + gb + kvg1);
            cp_commit();
            cp_wait<1>();
        } else {
            cp_wait<0>();
        }
        __syncthreads();

        const uint32_t st = sb + AT_ST0 + (kt & 1) * AT_KV_STAGE;
        const uint32_t khB = st + ATK;
        const uint32_t vhB = st + ATV;

        // ---- S = (Qh + Ql) @ Kh^T (fp16x2) ----
        float s[8][4];
#pragma unroll
        for (int j = 0; j < 8; j++)
#pragma unroll
            for (int r = 0; r < 4; r++) s[j][r] = 0.f;

#pragma unroll
        for (int k = 0; k < 4; k++) {
            uint32_t qh[4], ql[4];
            uint32_t qoff = (uint32_t)((wid * 16 + lrow) * QP + k * 16 + lsel) * 2;
            ldm_x4(qh, qhB + qoff);
            ldm_x4(ql, qlB + qoff);
#pragma unroll
            for (int nb = 0; nb < 4; nb++) {
                uint32_t kh[4];
                uint32_t koff = (uint32_t)((nb * 16 + lrow) * KVP + k * 16 + lsel) * 2;
                ldm_x4(kh, khB + koff);
                uint32_t b0[2] = {kh[0], kh[2]}, b1[2] = {kh[1], kh[3]};
                mma16816h(s[nb * 2], qh, b0);
                mma16816h(s[nb * 2], ql, b0);
                mma16816h(s[nb * 2 + 1], qh, b1);
                mma16816h(s[nb * 2 + 1], ql, b1);
            }
        }

        // ---- padding mask (only the last, partial tile needs it) ----
        if (kv0 + 64 > cntb) {
#pragma unroll
            for (int j = 0; j < 8; j++) {
                int col0 = kv0 + j * 8 + qc;
                float mk0 = (col0 < cntb) ? 0.f : -1.0e10f;
                float mk1 = (col0 + 1 < cntb) ? 0.f : -1.0e10f;
                s[j][0] += mk0; s[j][1] += mk1;
                s[j][2] += mk0; s[j][3] += mk1;
            }
        }

        // ---- warp-local online softmax ----
        float mt0 = -3.0e38f, mt1 = -3.0e38f;
#pragma unroll
        for (int j = 0; j < 8; j++) {
            mt0 = fmaxf(mt0, fmaxf(s[j][0], s[j][1]));
            mt1 = fmaxf(mt1, fmaxf(s[j][2], s[j][3]));
        }
        mt0 = fmaxf(mt0, __shfl_xor_sync(0xFFFFFFFF, mt0, 1));
        mt0 = fmaxf(mt0, __shfl_xor_sync(0xFFFFFFFF, mt0, 2));
        mt1 = fmaxf(mt1, __shfl_xor_sync(0xFFFFFFFF, mt1, 1));
        mt1 = fmaxf(mt1, __shfl_xor_sync(0xFFFFFFFF, mt1, 2));

        float mn0 = fmaxf(m0v, mt0), mn1 = fmaxf(m1v, mt1);
        float corr0 = __expf(m0v - mn0), corr1 = __expf(m1v - mn1);
        m0v = mn0; m1v = mn1;

        float ts0 = 0.f, ts1 = 0.f;
#pragma unroll
        for (int j = 0; j < 8; j++) {
            s[j][0] = __expf(s[j][0] - mn0);
            s[j][1] = __expf(s[j][1] - mn0);
            s[j][2] = __expf(s[j][2] - mn1);
            s[j][3] = __expf(s[j][3] - mn1);
            ts0 += s[j][0] + s[j][1];
            ts1 += s[j][2] + s[j][3];
        }
        ts0 += __shfl_xor_sync(0xFFFFFFFF, ts0, 1);
        ts0 += __shfl_xor_sync(0xFFFFFFFF, ts0, 2);
        ts1 += __shfl_xor_sync(0xFFFFFFFF, ts1, 1);
        ts1 += __shfl_xor_sync(0xFFFFFFFF, ts1, 2);
        l0v = l0v * corr0 + ts0;
        l1v = l1v * corr1 + ts1;

#pragma unroll
        for (int j = 0; j < 8; j++) {
            o[j][0] *= corr0; o[j][1] *= corr0;
            o[j][2] *= corr1; o[j][3] *= corr1;
        }

        // ---- O += Ph @ Vh (P truncated to fp16; no lo term) ----
#pragma unroll
        for (int t = 0; t < 4; t++) {
            uint32_t pah[4];
            pah[0] = pack_h(s[2 * t][0],     s[2 * t][1]);
            pah[1] = pack_h(s[2 * t][2],     s[2 * t][3]);
            pah[2] = pack_h(s[2 * t + 1][0], s[2 * t + 1][1]);
            pah[3] = pack_h(s[2 * t + 1][2], s[2 * t + 1][3]);
#pragma unroll
            for (int nb = 0; nb < 4; nb++) {
                uint32_t vh[4];
                uint32_t voff = (uint32_t)((t * 16 + lrow) * KVP + nb * 16 + lsel) * 2;
                ldm_x4t(vh, vhB + voff);
                mma16816h(o[nb * 2], pah, vh);
                mma16816h(o[nb * 2 + 1], pah, vh + 2);
            }
        }
        __syncthreads();
    }

    // ---- epilogue: normalize, split bf16 hi/lo for out-proj ----
    float inv0 = 1.f / l0v, inv1 = 1.f / l1v;
    const int r0g = q0 + wid * 16 + qr;
#pragma unroll
    for (int j = 0; j < 8; j++) {
        const size_t col = headoff + j * 8 + qc;
        float v00 = o[j][0] * inv0, v01 = o[j][1] * inv0;
        float v10 = o[j][2] * inv1, v11 = o[j][3] * inv1;
        __nv_bfloat162 h0 = __floats2bfloat162_rn(v00, v01);
        __nv_bfloat162 l0 = __floats2bfloat162_rn(v00 - __bfloat162float(h0.x),
                                                  v01 - __bfloat162float(h0.y));
        __nv_bfloat162 h1 = __floats2bfloat162_rn(v10, v11);
        __nv_bfloat162 l1 = __floats2bfloat162_rn(v10 - __bfloat162float(h1.x),
                                                  v11 - __bfloat162float(h1.y));
        *(__nv_bfloat162*)(Oh_ + ((size_t)b * SS + r0g) * DD + col)     = h0;
        *(__nv_bfloat162*)(Ol_ + ((size_t)b * SS + r0g) * DD + col)     = l0;
        *(__nv_bfloat162*)(Oh_ + ((size_t)b * SS + r0g + 8) * DD + col) = h1;
        *(__nv_bfloat162*)(Ol_ + ((size_t)b * SS + r0g + 8) * DD + col) = l1;
    }
}

// ---------------------------------------------------------------------------
extern "C" void kernel_launch(void* const* d_in, const int* in_sizes, int n_in,
                              void* d_out, int out_size)
{
    const float* q    = (const float*)d_in[0];
    const float* k    = (const float*)d_in[1];
    const float* v    = (const float*)d_in[2];
    const int*   mask = (const int*)d_in[3];
    const float* Wq   = (const float*)d_in[4];
    const float* bq   = (const float*)d_in[5];
    const float* Wk   = (const float*)d_in[6];
    const float* bk   = (const float*)d_in[7];
    const float* Wv   = (const float*)d_in[8];
    const float* bv   = (const float*)d_in[9];
    const float* Wo   = (const float*)d_in[10];
    const float* bo   = (const float*)d_in[11];
    float* out = (float*)d_out;

    __nv_bfloat16 *qh, *ql, *kch, *kcl, *vch, *vcl;
    __nv_bfloat16 *wqh, *wql, *wkh, *wkl, *wvh, *wvl, *woh, *wol;
    __nv_bfloat16 *ah, *al;
    __half *qph, *qpl, *kph, *vph;
    int *cidx, *cnt;
    cudaGetSymbolAddress((void**)&qh, g_qh);     cudaGetSymbolAddress((void**)&ql, g_ql);
    cudaGetSymbolAddress((void**)&kch, g_kc_h);  cudaGetSymbolAddress((void**)&kcl, g_kc_l);
    cudaGetSymbolAddress((void**)&vch, g_vc_h);  cudaGetSymbolAddress((void**)&vcl, g_vc_l);
    cudaGetSymbolAddress((void**)&wqh, g_wqh);   cudaGetSymbolAddress((void**)&wql, g_wql);
    cudaGetSymbolAddress((void**)&wkh, g_wkh);   cudaGetSymbolAddress((void**)&wkl, g_wkl);
    cudaGetSymbolAddress((void**)&wvh, g_wvh);   cudaGetSymbolAddress((void**)&wvl, g_wvl);
    cudaGetSymbolAddress((void**)&woh, g_woh);   cudaGetSymbolAddress((void**)&wol, g_wol);
    cudaGetSymbolAddress((void**)&qph, g_qph);   cudaGetSymbolAddress((void**)&qpl, g_qpl);
    cudaGetSymbolAddress((void**)&kph, g_kph);
    cudaGetSymbolAddress((void**)&vph, g_vph);
    cudaGetSymbolAddress((void**)&ah, g_ah);     cudaGetSymbolAddress((void**)&al, g_al);
    cudaGetSymbolAddress((void**)&cidx, g_cidx);
    cudaGetSymbolAddress((void**)&cnt, g_cnt);

    cudaFuncSetAttribute(gemm16_qkv_kernel,
                         cudaFuncAttributeMaxDynamicSharedMemorySize, G_SMEM);
    cudaFuncSetAttribute(gemm16_f32out_kernel,
                         cudaFuncAttributeMaxDynamicSharedMemorySize, G_SMEM);
    cudaFuncSetAttribute(attn_mma_kernel,
                         cudaFuncAttributeMaxDynamicSharedMemorySize, AT_SMEM);

    compact_kernel<<<BB, 256>>>(mask, cidx, cnt);
    split_all_kernel<<<dim3(4096, 6), 256>>>(q, k, v, Wq, Wk, Wv, Wo, cidx, cnt,
                                             qh, ql, kch, kcl, vch, vcl,
                                             wqh, wql, wkh, wkl,
                                             wvh, wvl, woh, wol);

    gemm16_qkv_kernel<<<dim3(8, 32, 3), 256, G_SMEM>>>(
        qh, ql, kch, kcl, vch, vcl,
        wqh, wql, wkh, wkl, wvh, wvl,
        bq, bk, bv,
        qph, qpl, kph, vph,
        cnt, BB * SS, DD, DD);

    attn_mma_kernel<<<dim3(SS / 128, BB * HH), 256, AT_SMEM>>>(
        qph, qpl, kph, vph, cnt, ah, al);

    dim3 gb(DD / 128, (BB * SS) / 128);
    gemm16_f32out_kernel<<<gb, 256, G_SMEM>>>(ah, al, woh, wol, bo, out, BB * SS, DD, DD);
}